// round 9
// baseline (speedup 1.0000x reference)
#include <cuda_runtime.h>
#include <cuda_fp16.h>
#include <cstddef>
#include <cstdint>

// ---------------- Problem constants ----------------
#define NNODES   131072        // B*2*NN
#define HDIM     256
#define EMBD     64
#define NEDGE    1000000
#define NGROUP   2048          // B*2
#define CARD     100

// ---------------- Scratch (no allocs allowed) ----------------
__device__ __align__(16) __half g_h0 [NNODES * EMBD];
__device__ __align__(16) __half g_z  [NNODES * HDIM];  // fused z = (1+eps)*h + agg
__device__ __align__(16) __half g_hA [NNODES * HDIM];  // node features (fp16)
__device__ int   g_deg[NNODES + 1];
__device__ int   g_off[NNODES + 1];
__device__ int   g_cur[NNODES];
__device__ int   g_srcl[NEDGE];
// fp16 fragment-ordered weights: per k16 block: 256 cols x 4 tg, uint2 {lo-pair, hi-pair}
__device__ uint2 g_wf16[(4 + 16 + 16 + 16) * 1024];

// ---------------- Helpers ----------------
__device__ __forceinline__ uint32_t h2u(__half2 h) {
    return *reinterpret_cast<uint32_t*>(&h);
}
__device__ __forceinline__ float2 u2f2(uint32_t u) {
    return __half22float2(*reinterpret_cast<__half2*>(&u));
}

__device__ __forceinline__ void mma_f16(float (&c)[4], const uint4& a,
                                        uint32_t b0, uint32_t b1) {
    asm volatile(
        "mma.sync.aligned.m16n8k16.row.col.f32.f16.f16.f32 "
        "{%0,%1,%2,%3}, {%4,%5,%6,%7}, {%8,%9}, {%0,%1,%2,%3};"
        : "+f"(c[0]), "+f"(c[1]), "+f"(c[2]), "+f"(c[3])
        : "r"(a.x), "r"(a.y), "r"(a.z), "r"(a.w), "r"(b0), "r"(b1));
}

// ---------------- Weight pre-convert: [K,256] fp32 -> fp16 fragment order ----------------
__global__ void wcvt16_kernel(const float* __restrict__ W, uint2* __restrict__ out,
                              int k16count)
{
    int idx = blockIdx.x * blockDim.x + threadIdx.x;
    if (idx >= k16count * 1024) return;
    int tg  = idx & 3;
    int col = (idx >> 2) & 255;
    int k16 = idx >> 10;
    int kr  = k16 * 16;
    __half2 lo = __floats2half2_rn(W[(kr + 2 * tg)     * 256 + col],
                                   W[(kr + 2 * tg + 1) * 256 + col]);
    __half2 hi = __floats2half2_rn(W[(kr + 2 * tg + 8) * 256 + col],
                                   W[(kr + 2 * tg + 9) * 256 + col]);
    out[idx] = make_uint2(h2u(lo), h2u(hi));
}

// ---------------- Embedding gather (fp32 table -> fp16 h0) ----------------
__global__ void embed_kernel(const int* __restrict__ x,
                             const float* __restrict__ table,
                             __half* __restrict__ h0)
{
    int idx = blockIdx.x * blockDim.x + threadIdx.x;   // NNODES * 8 (8 halves each)
    if (idx >= NNODES * 8) return;
    int n  = idx >> 3;
    int c8 = idx & 7;
    int b   = n >> 7;
    int col = n & 127;
    int row = x[(b << 7) + col] + col * CARD;
    const float4* src = (const float4*)(table + (size_t)row * 64) + c8 * 2;
    float4 a = __ldg(src);
    float4 c = __ldg(src + 1);
    uint4 o;
    o.x = h2u(__floats2half2_rn(a.x, a.y));
    o.y = h2u(__floats2half2_rn(a.z, a.w));
    o.z = h2u(__floats2half2_rn(c.x, c.y));
    o.w = h2u(__floats2half2_rn(c.z, c.w));
    ((uint4*)h0)[idx] = o;
}

// ---------------- CSR build ----------------
__global__ void hist_kernel(const int* __restrict__ ei, int* __restrict__ deg)
{
    int e = blockIdx.x * blockDim.x + threadIdx.x;
    if (e < NEDGE) atomicAdd(deg + ei[NEDGE + e], 1);
}

__global__ void scan_kernel(const int* __restrict__ deg,
                            int* __restrict__ off, int* __restrict__ cur)
{
    __shared__ int ps[1024];
    const int t = threadIdx.x;
    const int base = t * 128;
    int s = 0;
#pragma unroll 8
    for (int i = 0; i < 128; i++) s += deg[base + i];
    ps[t] = s;
    __syncthreads();
    for (int o = 1; o < 1024; o <<= 1) {
        int v = (t >= o) ? ps[t - o] : 0;
        __syncthreads();
        ps[t] += v;
        __syncthreads();
    }
    int run = ps[t] - s;
#pragma unroll 8
    for (int i = 0; i < 128; i++) {
        int d = deg[base + i];
        off[base + i] = run;
        cur[base + i] = run;
        run += d;
    }
    if (t == 1023) off[NNODES] = run;
}

__global__ void fill_kernel(const int* __restrict__ ei,
                            int* __restrict__ cur, int* __restrict__ srcl)
{
    int e = blockIdx.x * blockDim.x + threadIdx.x;
    if (e >= NEDGE) return;
    int d = ei[NEDGE + e];
    int pos = atomicAdd(cur + d, 1);
    srcl[pos] = ei[e];
}

// ---------------- Fused gather + z (fp16, MLP=2 neighbor loop) ----------------
// z[n] = (1+eps)*h[n] + sum_{s in nbr(n)} h[s]
template<int D>   // halves per row
__global__ void gather_z_kernel(const int* __restrict__ off,
                                const int* __restrict__ srcl,
                                const __half* __restrict__ hin,
                                __half* __restrict__ z,
                                const float* __restrict__ epsArr, int layer)
{
    constexpr int TPN = D / 8;      // uint4 (8 halves) per thread
    int gid  = blockIdx.x * blockDim.x + threadIdx.x;
    int node = gid / TPN;
    int sub  = gid % TPN;
    if (node >= NNODES) return;
    const float ope = 1.0f + epsArr[layer];
    int beg = off[node], end = off[node + 1];
    const uint4* hu = (const uint4*)hin;
    float a[8];
    {
        uint4 v = __ldg(hu + (size_t)node * TPN + sub);
        float2 f0 = u2f2(v.x), f1 = u2f2(v.y), f2 = u2f2(v.z), f3 = u2f2(v.w);
        a[0] = ope * f0.x; a[1] = ope * f0.y;
        a[2] = ope * f1.x; a[3] = ope * f1.y;
        a[4] = ope * f2.x; a[5] = ope * f2.y;
        a[6] = ope * f3.x; a[7] = ope * f3.y;
    }
    int p = beg;
    for (; p + 2 <= end; p += 2) {        // two independent row loads in flight
        int s0 = __ldg(srcl + p);
        int s1 = __ldg(srcl + p + 1);
        uint4 v0 = __ldg(hu + (size_t)s0 * TPN + sub);
        uint4 v1 = __ldg(hu + (size_t)s1 * TPN + sub);
        float2 f0 = u2f2(v0.x), f1 = u2f2(v0.y), f2 = u2f2(v0.z), f3 = u2f2(v0.w);
        float2 g0 = u2f2(v1.x), g1 = u2f2(v1.y), g2 = u2f2(v1.z), g3 = u2f2(v1.w);
        a[0] += f0.x + g0.x; a[1] += f0.y + g0.y;
        a[2] += f1.x + g1.x; a[3] += f1.y + g1.y;
        a[4] += f2.x + g2.x; a[5] += f2.y + g2.y;
        a[6] += f3.x + g3.x; a[7] += f3.y + g3.y;
    }
    if (p < end) {
        uint4 v = __ldg(hu + (size_t)__ldg(srcl + p) * TPN + sub);
        float2 f0 = u2f2(v.x), f1 = u2f2(v.y), f2 = u2f2(v.z), f3 = u2f2(v.w);
        a[0] += f0.x; a[1] += f0.y;
        a[2] += f1.x; a[3] += f1.y;
        a[4] += f2.x; a[5] += f2.y;
        a[6] += f3.x; a[7] += f3.y;
    }
    uint4 o;
    o.x = h2u(__floats2half2_rn(a[0], a[1]));
    o.y = h2u(__floats2half2_rn(a[2], a[3]));
    o.z = h2u(__floats2half2_rn(a[4], a[5]));
    o.w = h2u(__floats2half2_rn(a[6], a[7]));
    ((uint4*)z)[(size_t)node * TPN + sub] = o;
}

// ---------------- Fused GIN layer, fp16 m16n8k16 tensor cores ----------------
// Block = 512 threads = 16 warps; 64 rows x 256 cols. Warp w owns cols [w*16, w*16+16).
// __launch_bounds__(512, 2): cap regs at 64 so 2 CTAs/SM co-reside (2 x 103KB smem fits).

// SMEM float offsets
#define SPBA   0
#define SPG    256
#define SPB    512
#define AF_OFF 768                 // 8448 uint32 (16 k16 * 4 mt * 33-pad * 4)
#define TS_OFF (768 + 8448)        // 64 * 260 floats
#define GIN_SMEM_F (TS_OFF + 64 * 260)

template<int K>
__global__ void __launch_bounds__(512, 2)
gin_f16_kernel(const __half* __restrict__ z,
               const uint2* __restrict__ Waf, const float* __restrict__ ba,
               const float* __restrict__ gam,  const float* __restrict__ bet,
               const uint2* __restrict__ Wbf, const float* __restrict__ bb,
               __half* __restrict__ hout)
{
    extern __shared__ float smem[];
    uint32_t* AfU = (uint32_t*)(smem + AF_OFF);
    float*    Ts  = smem + TS_OFF;

    const int t    = threadIdx.x;
    const int lane = t & 31;
    const int warp = t >> 5;
    const int g    = lane >> 2;
    const int tg   = lane & 3;
    const int wb   = warp * 16;
    const int rowBase = blockIdx.x * 64;

    if (t < 256) { smem[SPBA + t] = ba[t]; smem[SPG + t] = gam[t]; smem[SPB + t] = bet[t]; }

    // ---- Stage Af: fp16 z -> fragment order (pure shuffle, no convert) ----
    {
        constexpr int U4R = K / 8;              // uint4 per row
        constexpr int NIT = 64 * U4R / 512;     // 1 (K=64) or 4 (K=256)
        const uint4* zU = (const uint4*)z;
#pragma unroll
        for (int j = 0; j < NIT; j++) {
            int i4  = t + 512 * j;
            int row = i4 / U4R;
            int pos = i4 % U4R;
            uint4 v = zU[(size_t)(rowBase + row) * U4R + pos];
            int mt = row >> 4;
            int r  = row & 15;
            int g2 = r & 7;
            int qr = r >> 3;
            int k16 = pos >> 1;
            int hi  = pos & 1;
            uint32_t* base = AfU + (((k16 * 4 + mt) * 33) + g2 * 4) * 4 + qr + 2 * hi;
            base[0]  = v.x;   // tgs 0
            base[4]  = v.y;   // tgs 1
            base[8]  = v.z;   // tgs 2
            base[12] = v.w;   // tgs 3
        }
    }
    __syncthreads();

    float C[4][2][4];
#pragma unroll
    for (int mt = 0; mt < 4; mt++)
#pragma unroll
        for (int nt = 0; nt < 2; nt++)
#pragma unroll
            for (int q = 0; q < 4; q++) C[mt][nt][q] = 0.0f;

    const int iA = (wb + g) * 4 + tg;
    const int iB = iA + 32;

    // ---- Phase 1: Af @ Waf ----
    {
        constexpr int K16 = K / 16;
        uint2 b0 = __ldg(Waf + iA);
        uint2 b1 = __ldg(Waf + iB);
#pragma unroll
        for (int k16 = 0; k16 < K16; k16++) {
            uint2 n0 = b0, n1 = b1;
            if (k16 + 1 < K16) {
                n0 = __ldg(Waf + (k16 + 1) * 1024 + iA);
                n1 = __ldg(Waf + (k16 + 1) * 1024 + iB);
            }
#pragma unroll
            for (int mt = 0; mt < 4; mt++) {
                uint4 a = *(const uint4*)(AfU + ((k16 * 4 + mt) * 33 + lane) * 4);
                mma_f16(C[mt][0], a, b0.x, b0.y);
                mma_f16(C[mt][1], a, b1.x, b1.y);
            }
            b0 = n0; b1 = n1;
        }
    }

    // ---- store C frags to Ts (row-major, padded 260) ----
#pragma unroll
    for (int mt = 0; mt < 4; mt++)
#pragma unroll
        for (int nt = 0; nt < 2; nt++) {
            int r0  = mt * 16 + g;
            int col = wb + nt * 8 + 2 * tg;
            *(float2*)(Ts +  r0      * 260 + col) = make_float2(C[mt][nt][0], C[mt][nt][1]);
            *(float2*)(Ts + (r0 + 8) * 260 + col) = make_float2(C[mt][nt][2], C[mt][nt][3]);
        }
    __syncthreads();

    // ---- bias + LayerNorm + ReLU -> Af (fp16 fragment order) ----
    if (t < 256) {
        int row = t >> 2;
        int q   = t & 3;
        float s = 0.0f, s2 = 0.0f;
#pragma unroll
        for (int c = 0; c < 32; c++) {
            float2 tv = *(const float2*)(Ts + row * 260 + 2 * q + 8 * c);
            float2 bv = *(const float2*)(smem + SPBA + 2 * q + 8 * c);
            float v0 = tv.x + bv.x, v1 = tv.y + bv.y;
            s += v0 + v1;
            s2 = fmaf(v0, v0, fmaf(v1, v1, s2));
        }
        s  += __shfl_xor_sync(0xffffffffu, s, 1);
        s  += __shfl_xor_sync(0xffffffffu, s, 2);
        s2 += __shfl_xor_sync(0xffffffffu, s2, 1);
        s2 += __shfl_xor_sync(0xffffffffu, s2, 2);
        float mean = s * (1.0f / 256.0f);
        float var  = s2 * (1.0f / 256.0f) - mean * mean;
        float inv  = rsqrtf(var + 1e-5f);
        int mt = row >> 4;
        int r  = row & 15;
        int g2 = r & 7;
        int qr = r >> 3;
#pragma unroll
        for (int c = 0; c < 32; c++) {
            float2 tv = *(const float2*)(Ts + row * 260 + 2 * q + 8 * c);
            float2 bv = *(const float2*)(smem + SPBA + 2 * q + 8 * c);
            float2 gv = *(const float2*)(smem + SPG  + 2 * q + 8 * c);
            float2 ev = *(const float2*)(smem + SPB  + 2 * q + 8 * c);
            float v0 = fmaf((tv.x + bv.x - mean) * inv, gv.x, ev.x);
            float v1 = fmaf((tv.y + bv.y - mean) * inv, gv.y, ev.y);
            v0 = fmaxf(v0, 0.0f);
            v1 = fmaxf(v1, 0.0f);
            int p   = q + 4 * c;
            int k16 = p >> 3;
            int hi  = c & 1;
            __half2 hv = __floats2half2_rn(v0, v1);
            AfU[(((k16 * 4 + mt) * 33) + g2 * 4 + q) * 4 + qr + 2 * hi] = h2u(hv);
        }
    }
    __syncthreads();

    // ---- Phase 2: Af(=T) @ Wbf ----
#pragma unroll
    for (int mt = 0; mt < 4; mt++)
#pragma unroll
        for (int nt = 0; nt < 2; nt++)
#pragma unroll
            for (int q = 0; q < 4; q++) C[mt][nt][q] = 0.0f;

    {
        uint2 b0 = __ldg(Wbf + iA);
        uint2 b1 = __ldg(Wbf + iB);
#pragma unroll
        for (int k16 = 0; k16 < 16; k16++) {
            uint2 n0 = b0, n1 = b1;
            if (k16 + 1 < 16) {
                n0 = __ldg(Wbf + (k16 + 1) * 1024 + iA);
                n1 = __ldg(Wbf + (k16 + 1) * 1024 + iB);
            }
#pragma unroll
            for (int mt = 0; mt < 4; mt++) {
                uint4 a = *(const uint4*)(AfU + ((k16 * 4 + mt) * 33 + lane) * 4);
                mma_f16(C[mt][0], a, b0.x, b0.y);
                mma_f16(C[mt][1], a, b1.x, b1.y);
            }
            b0 = n0; b1 = n1;
        }
    }

    // ---- + bb, store fp16 to global ----
    {
        uint32_t* ho = (uint32_t*)hout;
#pragma unroll
        for (int mt = 0; mt < 4; mt++)
#pragma unroll
            for (int nt = 0; nt < 2; nt++) {
                int r0  = rowBase + mt * 16 + g;
                int col = wb + nt * 8 + 2 * tg;
                float2 bbv = *(const float2*)(bb + col);
                __half2 o0 = __floats2half2_rn(C[mt][nt][0] + bbv.x, C[mt][nt][1] + bbv.y);
                __half2 o1 = __floats2half2_rn(C[mt][nt][2] + bbv.x, C[mt][nt][3] + bbv.y);
                ho[(size_t) r0      * 128 + (col >> 1)] = h2u(o0);
                ho[(size_t)(r0 + 8) * 128 + (col >> 1)] = h2u(o1);
            }
    }
}

// ---------------- Final group reduction (fp16 in, fp32 out) ----------------
__global__ void reduce_kernel(const __half* __restrict__ h, float* __restrict__ out)
{
    int idx = blockIdx.x * blockDim.x + threadIdx.x;   // NGROUP * 32 (8 halves each)
    if (idx >= NGROUP * 32) return;
    int g  = idx >> 5;
    int c8 = idx & 31;
    const uint4* p = (const uint4*)h + (size_t)g * 64 * 32 + c8;
    float a[8] = {0, 0, 0, 0, 0, 0, 0, 0};
#pragma unroll 8
    for (int j = 0; j < 64; j++) {
        uint4 v = p[(size_t)j * 32];
        float2 f0 = u2f2(v.x), f1 = u2f2(v.y), f2 = u2f2(v.z), f3 = u2f2(v.w);
        a[0] += f0.x; a[1] += f0.y; a[2] += f1.x; a[3] += f1.y;
        a[4] += f2.x; a[5] += f2.y; a[6] += f3.x; a[7] += f3.y;
    }
    float4* o = (float4*)(out + (size_t)g * 256 + c8 * 8);
    o[0] = make_float4(a[0], a[1], a[2], a[3]);
    o[1] = make_float4(a[4], a[5], a[6], a[7]);
}

// ---------------- Launch ----------------
extern "C" void kernel_launch(void* const* d_in, const int* in_sizes, int n_in,
                              void* d_out, int out_size)
{
    const int*   x     = (const int*)  d_in[0];
    const int*   ei    = (const int*)  d_in[1];
    const float* table = (const float*)d_in[3];
    const float* W0a   = (const float*)d_in[4];
    const float* b0a   = (const float*)d_in[5];
    const float* g0    = (const float*)d_in[6];
    const float* be0   = (const float*)d_in[7];
    const float* W0b   = (const float*)d_in[8];
    const float* b0b   = (const float*)d_in[9];
    const float* Wha   = (const float*)d_in[10];
    const float* bha   = (const float*)d_in[11];
    const float* gh    = (const float*)d_in[12];
    const float* beh   = (const float*)d_in[13];
    const float* Whb   = (const float*)d_in[14];
    const float* bhb   = (const float*)d_in[15];
    const float* eps   = (const float*)d_in[16];

    __half *h0, *z, *hA;
    int *deg, *off, *cur, *srcl;
    uint2 *wf;
    cudaGetSymbolAddress((void**)&h0,   g_h0);
    cudaGetSymbolAddress((void**)&z,    g_z);
    cudaGetSymbolAddress((void**)&hA,   g_hA);
    cudaGetSymbolAddress((void**)&deg,  g_deg);
    cudaGetSymbolAddress((void**)&off,  g_off);
    cudaGetSymbolAddress((void**)&cur,  g_cur);
    cudaGetSymbolAddress((void**)&srcl, g_srcl);
    cudaGetSymbolAddress((void**)&wf,   g_wf16);

    uint2* W0af = wf;               // 4 k16 blocks
    uint2* W0bf = wf + 4  * 1024;   // 16
    uint2* Whaf = wf + 20 * 1024;   // 16
    uint2* Whbf = wf + 36 * 1024;   // 16

    const int SMEM_BYTES = GIN_SMEM_F * (int)sizeof(float);
    cudaFuncSetAttribute((const void*)gin_f16_kernel<64>,
                         cudaFuncAttributeMaxDynamicSharedMemorySize, SMEM_BYTES);
    cudaFuncSetAttribute((const void*)gin_f16_kernel<256>,
                         cudaFuncAttributeMaxDynamicSharedMemorySize, SMEM_BYTES);

    // ---- Weight pre-convert (fp16 fragment order) ----
    wcvt16_kernel<<<(4  * 1024 + 255) / 256, 256>>>(W0a, W0af, 4);
    wcvt16_kernel<<<(16 * 1024 + 255) / 256, 256>>>(W0b, W0bf, 16);
    wcvt16_kernel<<<(16 * 1024 + 255) / 256, 256>>>(Wha, Whaf, 16);
    wcvt16_kernel<<<(16 * 1024 + 255) / 256, 256>>>(Whb, Whbf, 16);

    // ---- CSR build ----
    cudaMemsetAsync(deg, 0, (NNODES + 1) * sizeof(int));
    hist_kernel<<<(NEDGE + 255) / 256, 256>>>(ei, deg);
    scan_kernel<<<1, 1024>>>(deg, off, cur);
    fill_kernel<<<(NEDGE + 255) / 256, 256>>>(ei, cur, srcl);

    // ---- Embedding gather ----
    embed_kernel<<<(NNODES * 8 + 255) / 256, 256>>>(x, table, h0);

    // ---- Layer 0 (K = 64) ----
    gather_z_kernel<64><<<(NNODES * 8 + 255) / 256, 256>>>(off, srcl, h0, z, eps, 0);
    gin_f16_kernel<64><<<NNODES / 64, 512, SMEM_BYTES>>>(
        z, W0af, b0a, g0, be0, W0bf, b0b, hA);

    // ---- Layers 1..2 (K = 256) ----
    for (int l = 1; l < 3; l++) {
        gather_z_kernel<256><<<(NNODES * 32 + 255) / 256, 256>>>(off, srcl, hA, z, eps, l);
        gin_f16_kernel<256><<<NNODES / 64, 512, SMEM_BYTES>>>(
            z, Whaf, bha, gh, beh, Whbf, bhb, hA);
    }

    // ---- Final per-graph-node-group sum ----
    reduce_kernel<<<(NGROUP * 32 + 255) / 256, 256>>>(hA, (float*)d_out);
}

// round 10
// speedup vs baseline: 1.0146x; 1.0146x over previous
#include <cuda_runtime.h>
#include <cuda_fp16.h>
#include <cstddef>
#include <cstdint>

// ---------------- Problem constants ----------------
#define NNODES   131072        // B*2*NN
#define HDIM     256
#define EMBD     64
#define NEDGE    1000000
#define NGROUP   2048          // B*2
#define CARD     100

// ---------------- Scratch (no allocs allowed) ----------------
__device__ __align__(16) __half g_h0 [NNODES * EMBD];
__device__ __align__(16) __half g_z  [NNODES * HDIM];  // fused z = (1+eps)*h + agg
__device__ __align__(16) __half g_hA [NNODES * HDIM];  // node features (fp16)
__device__ int   g_deg[NNODES + 1];
__device__ int   g_off[NNODES + 1];
__device__ int   g_cur[NNODES];
__device__ int   g_srcl[NEDGE];
// fp16 fragment-ordered weights: per k16 block: 256 cols x 4 tg, uint2 {lo-pair, hi-pair}
__device__ uint2 g_wf16[(4 + 16 + 16 + 16) * 1024];

// ---------------- Helpers ----------------
__device__ __forceinline__ uint32_t h2u(__half2 h) {
    return *reinterpret_cast<uint32_t*>(&h);
}
__device__ __forceinline__ float2 u2f2(uint32_t u) {
    return __half22float2(*reinterpret_cast<__half2*>(&u));
}

__device__ __forceinline__ void mma_f16(float (&c)[4], const uint4& a,
                                        uint32_t b0, uint32_t b1) {
    asm volatile(
        "mma.sync.aligned.m16n8k16.row.col.f32.f16.f16.f32 "
        "{%0,%1,%2,%3}, {%4,%5,%6,%7}, {%8,%9}, {%0,%1,%2,%3};"
        : "+f"(c[0]), "+f"(c[1]), "+f"(c[2]), "+f"(c[3])
        : "r"(a.x), "r"(a.y), "r"(a.z), "r"(a.w), "r"(b0), "r"(b1));
}

// ---------------- Weight pre-convert: [K,256] fp32 -> fp16 fragment order ----------------
__global__ void wcvt16_kernel(const float* __restrict__ W, uint2* __restrict__ out,
                              int k16count)
{
    int idx = blockIdx.x * blockDim.x + threadIdx.x;
    if (idx >= k16count * 1024) return;
    int tg  = idx & 3;
    int col = (idx >> 2) & 255;
    int k16 = idx >> 10;
    int kr  = k16 * 16;
    __half2 lo = __floats2half2_rn(W[(kr + 2 * tg)     * 256 + col],
                                   W[(kr + 2 * tg + 1) * 256 + col]);
    __half2 hi = __floats2half2_rn(W[(kr + 2 * tg + 8) * 256 + col],
                                   W[(kr + 2 * tg + 9) * 256 + col]);
    out[idx] = make_uint2(h2u(lo), h2u(hi));
}

// ---------------- Embedding gather (fp32 table -> fp16 h0) ----------------
__global__ void embed_kernel(const int* __restrict__ x,
                             const float* __restrict__ table,
                             __half* __restrict__ h0)
{
    int idx = blockIdx.x * blockDim.x + threadIdx.x;   // NNODES * 8 (8 halves each)
    if (idx >= NNODES * 8) return;
    int n  = idx >> 3;
    int c8 = idx & 7;
    int b   = n >> 7;
    int col = n & 127;
    int row = x[(b << 7) + col] + col * CARD;
    const float4* src = (const float4*)(table + (size_t)row * 64) + c8 * 2;
    float4 a = __ldg(src);
    float4 c = __ldg(src + 1);
    uint4 o;
    o.x = h2u(__floats2half2_rn(a.x, a.y));
    o.y = h2u(__floats2half2_rn(a.z, a.w));
    o.z = h2u(__floats2half2_rn(c.x, c.y));
    o.w = h2u(__floats2half2_rn(c.z, c.w));
    ((uint4*)h0)[idx] = o;
}

// ---------------- CSR build ----------------
__global__ void hist_kernel(const int* __restrict__ ei, int* __restrict__ deg)
{
    int e = blockIdx.x * blockDim.x + threadIdx.x;
    if (e < NEDGE) atomicAdd(deg + ei[NEDGE + e], 1);
}

__global__ void scan_kernel(const int* __restrict__ deg,
                            int* __restrict__ off, int* __restrict__ cur)
{
    __shared__ int ps[1024];
    const int t = threadIdx.x;
    const int base = t * 128;
    int s = 0;
#pragma unroll 8
    for (int i = 0; i < 128; i++) s += deg[base + i];
    ps[t] = s;
    __syncthreads();
    for (int o = 1; o < 1024; o <<= 1) {
        int v = (t >= o) ? ps[t - o] : 0;
        __syncthreads();
        ps[t] += v;
        __syncthreads();
    }
    int run = ps[t] - s;
#pragma unroll 8
    for (int i = 0; i < 128; i++) {
        int d = deg[base + i];
        off[base + i] = run;
        cur[base + i] = run;
        run += d;
    }
    if (t == 1023) off[NNODES] = run;
}

__global__ void fill_kernel(const int* __restrict__ ei,
                            int* __restrict__ cur, int* __restrict__ srcl)
{
    int e = blockIdx.x * blockDim.x + threadIdx.x;
    if (e >= NEDGE) return;
    int d = ei[NEDGE + e];
    int pos = atomicAdd(cur + d, 1);
    srcl[pos] = ei[e];
}

// ---------------- Fused gather + z (fp16, MLP=4 neighbor loop) ----------------
// z[n] = (1+eps)*h[n] + sum_{s in nbr(n)} h[s]
template<int D>   // halves per row
__global__ void gather_z_kernel(const int* __restrict__ off,
                                const int* __restrict__ srcl,
                                const __half* __restrict__ hin,
                                __half* __restrict__ z,
                                const float* __restrict__ epsArr, int layer)
{
    constexpr int TPN = D / 8;      // uint4 (8 halves) per thread
    int gid  = blockIdx.x * blockDim.x + threadIdx.x;
    int node = gid / TPN;
    int sub  = gid % TPN;
    if (node >= NNODES) return;
    const float ope = 1.0f + epsArr[layer];
    int beg = off[node], end = off[node + 1];
    const uint4* hu = (const uint4*)hin;
    float a[8];
    {
        uint4 v = __ldg(hu + (size_t)node * TPN + sub);
        float2 f0 = u2f2(v.x), f1 = u2f2(v.y), f2 = u2f2(v.z), f3 = u2f2(v.w);
        a[0] = ope * f0.x; a[1] = ope * f0.y;
        a[2] = ope * f1.x; a[3] = ope * f1.y;
        a[4] = ope * f2.x; a[5] = ope * f2.y;
        a[6] = ope * f3.x; a[7] = ope * f3.y;
    }
    int p = beg;
    for (; p + 4 <= end; p += 4) {        // four independent row loads in flight
        int s0 = __ldg(srcl + p);
        int s1 = __ldg(srcl + p + 1);
        int s2 = __ldg(srcl + p + 2);
        int s3 = __ldg(srcl + p + 3);
        uint4 v0 = __ldg(hu + (size_t)s0 * TPN + sub);
        uint4 v1 = __ldg(hu + (size_t)s1 * TPN + sub);
        uint4 v2 = __ldg(hu + (size_t)s2 * TPN + sub);
        uint4 v3 = __ldg(hu + (size_t)s3 * TPN + sub);
#pragma unroll
        for (int u = 0; u < 4; u++) {
            uint32_t w0 = (&v0.x)[u], w1 = (&v1.x)[u], w2 = (&v2.x)[u], w3 = (&v3.x)[u];
            float2 f0 = u2f2(w0), f1 = u2f2(w1), f2 = u2f2(w2), f3 = u2f2(w3);
            a[2 * u]     += (f0.x + f1.x) + (f2.x + f3.x);
            a[2 * u + 1] += (f0.y + f1.y) + (f2.y + f3.y);
        }
    }
    for (; p < end; p++) {
        uint4 v = __ldg(hu + (size_t)__ldg(srcl + p) * TPN + sub);
#pragma unroll
        for (int u = 0; u < 4; u++) {
            float2 f = u2f2((&v.x)[u]);
            a[2 * u] += f.x; a[2 * u + 1] += f.y;
        }
    }
    uint4 o;
    o.x = h2u(__floats2half2_rn(a[0], a[1]));
    o.y = h2u(__floats2half2_rn(a[2], a[3]));
    o.z = h2u(__floats2half2_rn(a[4], a[5]));
    o.w = h2u(__floats2half2_rn(a[6], a[7]));
    ((uint4*)z)[(size_t)node * TPN + sub] = o;
}

// ---------------- Fused GIN layer, fp16 m16n8k16 tensor cores ----------------
// Block = 512 threads = 16 warps; 64 rows x 256 cols. Warp w owns cols [w*16, w*16+16).
// FINAL variant: block's 64 rows = exactly one output group; epilogue reduces
// C fragments over rows (mt + both row-halves + shfl over g-lanes) and writes
// fp32 group sums (+64*bb) straight to d_out. Non-final writes fp16 hA.

// SMEM float offsets
#define SPBA   0
#define SPG    256
#define SPB    512
#define AF_OFF 768                 // 8448 uint32 (16 k16 * 4 mt * 33-pad * 4)
#define TS_OFF (768 + 8448)        // 64 * 260 floats
#define GIN_SMEM_F (TS_OFF + 64 * 260)

template<int K, bool FINAL>
__global__ void __launch_bounds__(512)
gin_f16_kernel(const __half* __restrict__ z,
               const uint2* __restrict__ Waf, const float* __restrict__ ba,
               const float* __restrict__ gam,  const float* __restrict__ bet,
               const uint2* __restrict__ Wbf, const float* __restrict__ bb,
               __half* __restrict__ hout, float* __restrict__ gout)
{
    extern __shared__ float smem[];
    uint32_t* AfU = (uint32_t*)(smem + AF_OFF);
    float*    Ts  = smem + TS_OFF;

    const int t    = threadIdx.x;
    const int lane = t & 31;
    const int warp = t >> 5;
    const int g    = lane >> 2;
    const int tg   = lane & 3;
    const int wb   = warp * 16;
    const int rowBase = blockIdx.x * 64;

    if (t < 256) { smem[SPBA + t] = ba[t]; smem[SPG + t] = gam[t]; smem[SPB + t] = bet[t]; }

    // ---- Stage Af: fp16 z -> fragment order (pure shuffle, no convert) ----
    {
        constexpr int U4R = K / 8;              // uint4 per row
        constexpr int NIT = 64 * U4R / 512;     // 1 (K=64) or 4 (K=256)
        const uint4* zU = (const uint4*)z;
#pragma unroll
        for (int j = 0; j < NIT; j++) {
            int i4  = t + 512 * j;
            int row = i4 / U4R;
            int pos = i4 % U4R;
            uint4 v = zU[(size_t)(rowBase + row) * U4R + pos];
            int mt = row >> 4;
            int r  = row & 15;
            int g2 = r & 7;
            int qr = r >> 3;
            int k16 = pos >> 1;
            int hi  = pos & 1;
            uint32_t* base = AfU + (((k16 * 4 + mt) * 33) + g2 * 4) * 4 + qr + 2 * hi;
            base[0]  = v.x;   // tgs 0
            base[4]  = v.y;   // tgs 1
            base[8]  = v.z;   // tgs 2
            base[12] = v.w;   // tgs 3
        }
    }
    __syncthreads();

    float C[4][2][4];
#pragma unroll
    for (int mt = 0; mt < 4; mt++)
#pragma unroll
        for (int nt = 0; nt < 2; nt++)
#pragma unroll
            for (int q = 0; q < 4; q++) C[mt][nt][q] = 0.0f;

    const int iA = (wb + g) * 4 + tg;
    const int iB = iA + 32;

    // ---- Phase 1: Af @ Waf ----
    {
        constexpr int K16 = K / 16;
        uint2 b0 = __ldg(Waf + iA);
        uint2 b1 = __ldg(Waf + iB);
#pragma unroll
        for (int k16 = 0; k16 < K16; k16++) {
            uint2 n0 = b0, n1 = b1;
            if (k16 + 1 < K16) {
                n0 = __ldg(Waf + (k16 + 1) * 1024 + iA);
                n1 = __ldg(Waf + (k16 + 1) * 1024 + iB);
            }
#pragma unroll
            for (int mt = 0; mt < 4; mt++) {
                uint4 a = *(const uint4*)(AfU + ((k16 * 4 + mt) * 33 + lane) * 4);
                mma_f16(C[mt][0], a, b0.x, b0.y);
                mma_f16(C[mt][1], a, b1.x, b1.y);
            }
            b0 = n0; b1 = n1;
        }
    }

    // ---- store C frags to Ts (row-major, padded 260) ----
#pragma unroll
    for (int mt = 0; mt < 4; mt++)
#pragma unroll
        for (int nt = 0; nt < 2; nt++) {
            int r0  = mt * 16 + g;
            int col = wb + nt * 8 + 2 * tg;
            *(float2*)(Ts +  r0      * 260 + col) = make_float2(C[mt][nt][0], C[mt][nt][1]);
            *(float2*)(Ts + (r0 + 8) * 260 + col) = make_float2(C[mt][nt][2], C[mt][nt][3]);
        }
    __syncthreads();

    // ---- bias + LayerNorm + ReLU -> Af (fp16 fragment order) ----
    if (t < 256) {
        int row = t >> 2;
        int q   = t & 3;
        float s = 0.0f, s2 = 0.0f;
#pragma unroll
        for (int c = 0; c < 32; c++) {
            float2 tv = *(const float2*)(Ts + row * 260 + 2 * q + 8 * c);
            float2 bv = *(const float2*)(smem + SPBA + 2 * q + 8 * c);
            float v0 = tv.x + bv.x, v1 = tv.y + bv.y;
            s += v0 + v1;
            s2 = fmaf(v0, v0, fmaf(v1, v1, s2));
        }
        s  += __shfl_xor_sync(0xffffffffu, s, 1);
        s  += __shfl_xor_sync(0xffffffffu, s, 2);
        s2 += __shfl_xor_sync(0xffffffffu, s2, 1);
        s2 += __shfl_xor_sync(0xffffffffu, s2, 2);
        float mean = s * (1.0f / 256.0f);
        float var  = s2 * (1.0f / 256.0f) - mean * mean;
        float inv  = rsqrtf(var + 1e-5f);
        int mt = row >> 4;
        int r  = row & 15;
        int g2 = r & 7;
        int qr = r >> 3;
#pragma unroll
        for (int c = 0; c < 32; c++) {
            float2 tv = *(const float2*)(Ts + row * 260 + 2 * q + 8 * c);
            float2 bv = *(const float2*)(smem + SPBA + 2 * q + 8 * c);
            float2 gv = *(const float2*)(smem + SPG  + 2 * q + 8 * c);
            float2 ev = *(const float2*)(smem + SPB  + 2 * q + 8 * c);
            float v0 = fmaf((tv.x + bv.x - mean) * inv, gv.x, ev.x);
            float v1 = fmaf((tv.y + bv.y - mean) * inv, gv.y, ev.y);
            v0 = fmaxf(v0, 0.0f);
            v1 = fmaxf(v1, 0.0f);
            int p   = q + 4 * c;
            int k16 = p >> 3;
            int hi  = c & 1;
            __half2 hv = __floats2half2_rn(v0, v1);
            AfU[(((k16 * 4 + mt) * 33) + g2 * 4 + q) * 4 + qr + 2 * hi] = h2u(hv);
        }
    }
    __syncthreads();

    // ---- Phase 2: Af(=T) @ Wbf ----
#pragma unroll
    for (int mt = 0; mt < 4; mt++)
#pragma unroll
        for (int nt = 0; nt < 2; nt++)
#pragma unroll
            for (int q = 0; q < 4; q++) C[mt][nt][q] = 0.0f;

    {
        uint2 b0 = __ldg(Wbf + iA);
        uint2 b1 = __ldg(Wbf + iB);
#pragma unroll
        for (int k16 = 0; k16 < 16; k16++) {
            uint2 n0 = b0, n1 = b1;
            if (k16 + 1 < 16) {
                n0 = __ldg(Wbf + (k16 + 1) * 1024 + iA);
                n1 = __ldg(Wbf + (k16 + 1) * 1024 + iB);
            }
#pragma unroll
            for (int mt = 0; mt < 4; mt++) {
                uint4 a = *(const uint4*)(AfU + ((k16 * 4 + mt) * 33 + lane) * 4);
                mma_f16(C[mt][0], a, b0.x, b0.y);
                mma_f16(C[mt][1], a, b1.x, b1.y);
            }
            b0 = n0; b1 = n1;
        }
    }

    if (!FINAL) {
        // ---- + bb, store fp16 to global ----
        uint32_t* ho = (uint32_t*)hout;
#pragma unroll
        for (int mt = 0; mt < 4; mt++)
#pragma unroll
            for (int nt = 0; nt < 2; nt++) {
                int r0  = rowBase + mt * 16 + g;
                int col = wb + nt * 8 + 2 * tg;
                float2 bbv = *(const float2*)(bb + col);
                __half2 o0 = __floats2half2_rn(C[mt][nt][0] + bbv.x, C[mt][nt][1] + bbv.y);
                __half2 o1 = __floats2half2_rn(C[mt][nt][2] + bbv.x, C[mt][nt][3] + bbv.y);
                ho[(size_t) r0      * 128 + (col >> 1)] = h2u(o0);
                ho[(size_t)(r0 + 8) * 128 + (col >> 1)] = h2u(o1);
            }
    } else {
        // ---- fused group reduction: sum over 64 rows, +64*bb, fp32 out ----
#pragma unroll
        for (int nt = 0; nt < 2; nt++) {
            float s0 = 0.0f, s1 = 0.0f;
#pragma unroll
            for (int mt = 0; mt < 4; mt++) {
                s0 += C[mt][nt][0] + C[mt][nt][2];
                s1 += C[mt][nt][1] + C[mt][nt][3];
            }
#pragma unroll
            for (int o = 4; o <= 16; o <<= 1) {
                s0 += __shfl_xor_sync(0xffffffffu, s0, o);
                s1 += __shfl_xor_sync(0xffffffffu, s1, o);
            }
            if (g == 0) {
                int col = wb + nt * 8 + 2 * tg;
                float2 bbv = *(const float2*)(bb + col);
                float2 o2 = make_float2(s0 + 64.0f * bbv.x, s1 + 64.0f * bbv.y);
                *(float2*)(gout + (size_t)blockIdx.x * 256 + col) = o2;
            }
        }
    }
}

// ---------------- Launch ----------------
extern "C" void kernel_launch(void* const* d_in, const int* in_sizes, int n_in,
                              void* d_out, int out_size)
{
    const int*   x     = (const int*)  d_in[0];
    const int*   ei    = (const int*)  d_in[1];
    const float* table = (const float*)d_in[3];
    const float* W0a   = (const float*)d_in[4];
    const float* b0a   = (const float*)d_in[5];
    const float* g0    = (const float*)d_in[6];
    const float* be0   = (const float*)d_in[7];
    const float* W0b   = (const float*)d_in[8];
    const float* b0b   = (const float*)d_in[9];
    const float* Wha   = (const float*)d_in[10];
    const float* bha   = (const float*)d_in[11];
    const float* gh    = (const float*)d_in[12];
    const float* beh   = (const float*)d_in[13];
    const float* Whb   = (const float*)d_in[14];
    const float* bhb   = (const float*)d_in[15];
    const float* eps   = (const float*)d_in[16];

    __half *h0, *z, *hA;
    int *deg, *off, *cur, *srcl;
    uint2 *wf;
    cudaGetSymbolAddress((void**)&h0,   g_h0);
    cudaGetSymbolAddress((void**)&z,    g_z);
    cudaGetSymbolAddress((void**)&hA,   g_hA);
    cudaGetSymbolAddress((void**)&deg,  g_deg);
    cudaGetSymbolAddress((void**)&off,  g_off);
    cudaGetSymbolAddress((void**)&cur,  g_cur);
    cudaGetSymbolAddress((void**)&srcl, g_srcl);
    cudaGetSymbolAddress((void**)&wf,   g_wf16);

    uint2* W0af = wf;               // 4 k16 blocks
    uint2* W0bf = wf + 4  * 1024;   // 16
    uint2* Whaf = wf + 20 * 1024;   // 16
    uint2* Whbf = wf + 36 * 1024;   // 16

    const int SMEM_BYTES = GIN_SMEM_F * (int)sizeof(float);
    cudaFuncSetAttribute((const void*)gin_f16_kernel<64, false>,
                         cudaFuncAttributeMaxDynamicSharedMemorySize, SMEM_BYTES);
    cudaFuncSetAttribute((const void*)gin_f16_kernel<256, false>,
                         cudaFuncAttributeMaxDynamicSharedMemorySize, SMEM_BYTES);
    cudaFuncSetAttribute((const void*)gin_f16_kernel<256, true>,
                         cudaFuncAttributeMaxDynamicSharedMemorySize, SMEM_BYTES);

    // ---- Weight pre-convert (fp16 fragment order) ----
    wcvt16_kernel<<<(4  * 1024 + 255) / 256, 256>>>(W0a, W0af, 4);
    wcvt16_kernel<<<(16 * 1024 + 255) / 256, 256>>>(W0b, W0bf, 16);
    wcvt16_kernel<<<(16 * 1024 + 255) / 256, 256>>>(Wha, Whaf, 16);
    wcvt16_kernel<<<(16 * 1024 + 255) / 256, 256>>>(Whb, Whbf, 16);

    // ---- CSR build ----
    cudaMemsetAsync(deg, 0, (NNODES + 1) * sizeof(int));
    hist_kernel<<<(NEDGE + 255) / 256, 256>>>(ei, deg);
    scan_kernel<<<1, 1024>>>(deg, off, cur);
    fill_kernel<<<(NEDGE + 255) / 256, 256>>>(ei, cur, srcl);

    // ---- Embedding gather ----
    embed_kernel<<<(NNODES * 8 + 255) / 256, 256>>>(x, table, h0);

    // ---- Layer 0 (K = 64) ----
    gather_z_kernel<64><<<(NNODES * 8 + 255) / 256, 256>>>(off, srcl, h0, z, eps, 0);
    gin_f16_kernel<64, false><<<NNODES / 64, 512, SMEM_BYTES>>>(
        z, W0af, b0a, g0, be0, W0bf, b0b, hA, nullptr);

    // ---- Layer 1 (K = 256) ----
    gather_z_kernel<256><<<(NNODES * 32 + 255) / 256, 256>>>(off, srcl, hA, z, eps, 1);
    gin_f16_kernel<256, false><<<NNODES / 64, 512, SMEM_BYTES>>>(
        z, Whaf, bha, gh, beh, Whbf, bhb, hA, nullptr);

    // ---- Layer 2 (K = 256) + fused group reduction -> d_out ----
    gather_z_kernel<256><<<(NNODES * 32 + 255) / 256, 256>>>(off, srcl, hA, z, eps, 2);
    gin_f16_kernel<256, true><<<NNODES / 64, 512, SMEM_BYTES>>>(
        z, Whaf, bha, gh, beh, Whbf, bhb, nullptr, (float*)d_out);
}